// round 10
// baseline (speedup 1.0000x reference)
#include <cuda_runtime.h>
#include <cuda_fp16.h>
#include <math.h>
#include <stdint.h>

#define MROWS 1024
#define KDIM  512
#define CCLS  85742
#define S_SCALE 64.0f
#define MARGIN  0.5f
#define EPS_CL  1e-7f

// GEMM tiling: 256x128 CTA tile, 256 threads (8 warps, 4 M x 2 N, warp 64x64)
// occupancy 1 CTA/SM, full 255-reg budget (128 acc regs/thread).
#define BM 256
#define BN 128
#define BK 64                    // k-halves per stage -> 128B per smem row
#define KSTAGES (KDIM / BK)      // 8
#define ROWB 128                 // bytes per smem row (SW128 swizzle)
#define AST (BM * ROWB)          // 32768
#define BST (BN * ROWB)          // 16384
#define STAGE_BYTES (AST + BST)  // 49152
#define NSTAGE 3                 // 144KB dynamic smem per CTA

#define NCHUNK8 ((size_t)CCLS * KDIM / 8)        // 16B-output chunks of W
#define CONVBLK ((int)((NCHUNK8 + 255) / 256))   // conv blocks (256 thr)

__device__ __half g_xnh[MROWS * KDIM];          // normalized x, fp16
__device__ __half g_wh[(size_t)CCLS * KDIM];    // W, fp16 (87.8 MB)
__device__ float  g_rowsum[MROWS];
__device__ float  g_loss;
__device__ int    g_isI64;

// ---------------------------------------------------------------------------
// helpers
// ---------------------------------------------------------------------------
__device__ __forceinline__ uint32_t smem_u32(const void* p) {
    uint32_t a;
    asm("{ .reg .u64 t; cvta.to.shared.u64 t, %1; cvt.u32.u64 %0, t; }"
        : "=r"(a) : "l"(p));
    return a;
}

// SW128 swizzle: row r (128B rows), 16B chunk c in [0,8)
__device__ __forceinline__ uint32_t swz(int r, int c) {
    return (uint32_t)(r * ROWB + ((c ^ (r & 7)) << 4));
}

__device__ __forceinline__ uint2 f4toh4(float4 v) {
    __half2 lo = __float22half2_rn(make_float2(v.x, v.y));
    __half2 hi = __float22half2_rn(make_float2(v.z, v.w));
    uint2 r;
    r.x = *reinterpret_cast<unsigned*>(&lo);
    r.y = *reinterpret_cast<unsigned*>(&hi);
    return r;
}

__device__ __forceinline__ void cp16(uint32_t dst, const void* src, uint32_t srcsz) {
    asm volatile("cp.async.cg.shared.global [%0], [%1], 16, %2;"
                 :: "r"(dst), "l"(src), "r"(srcsz) : "memory");
}
__device__ __forceinline__ void cp_commit() {
    asm volatile("cp.async.commit_group;" ::: "memory");
}
template <int N> __device__ __forceinline__ void cp_wait() {
    asm volatile("cp.async.wait_group %0;" :: "n"(N) : "memory");
}

__device__ __forceinline__ void ldsm4(uint32_t* r, uint32_t addr) {
    asm volatile("ldmatrix.sync.aligned.m8n8.x4.shared.b16 {%0,%1,%2,%3}, [%4];"
                 : "=r"(r[0]), "=r"(r[1]), "=r"(r[2]), "=r"(r[3]) : "r"(addr));
}

__device__ __forceinline__ void mma_f16(float* d, const uint32_t* a,
                                        uint32_t b0, uint32_t b1) {
    asm volatile(
        "mma.sync.aligned.m16n8k16.row.col.f32.f16.f16.f32 "
        "{%0,%1,%2,%3}, {%4,%5,%6,%7}, {%8,%9}, {%0,%1,%2,%3};"
        : "+f"(d[0]), "+f"(d[1]), "+f"(d[2]), "+f"(d[3])
        : "r"(a[0]), "r"(a[1]), "r"(a[2]), "r"(a[3]), "r"(b0), "r"(b1));
}

__device__ __forceinline__ void stg_cs2(float* p, float a, float b) {
    asm volatile("st.global.cs.v2.f32 [%0], {%1,%2};"
                 :: "l"(p), "f"(a), "f"(b) : "memory");
}

// ---------------------------------------------------------------------------
// Kernel 1 (prep): blocks [0,1024) L2-normalize one x-row each into g_xnh and
// zero g_rowsum (block 0 also zeroes g_loss and sniffs label dtype);
// blocks [1024, 1024+CONVBLK) convert W f32 -> fp16 (8 elems/thread, __ldcs).
// ---------------------------------------------------------------------------
__global__ void prep_kernel(const float* __restrict__ x,
                            const float* __restrict__ W,
                            const int* __restrict__ labels_raw) {
    int t = threadIdx.x;            // 256 threads
    if (blockIdx.x < MROWS) {
        int row = blockIdx.x;
        float s = 0.0f;
        float4 v = make_float4(0.f, 0.f, 0.f, 0.f);
        if (t < 128) {
            v = ((const float4*)(x + (size_t)row * KDIM))[t];
            s = v.x * v.x + v.y * v.y + v.z * v.z + v.w * v.w;
        }
        #pragma unroll
        for (int o = 16; o > 0; o >>= 1) s += __shfl_xor_sync(0xffffffffu, s, o);
        __shared__ float ws[8];
        int lane = t & 31, wid = t >> 5;
        if (lane == 0) ws[wid] = s;
        __syncthreads();
        float tot = ws[0] + ws[1] + ws[2] + ws[3];
        float inv = 1.0f / fmaxf(sqrtf(tot), 1e-12f);
        if (t < 128) {
            float4 o4 = make_float4(v.x * inv, v.y * inv, v.z * inv, v.w * inv);
            ((uint2*)(g_xnh + (size_t)row * KDIM))[t] = f4toh4(o4);
        }
        if (t == 0) g_rowsum[row] = 0.0f;

        if (row == 0) {
            // label dtype sniff on words [0,1024): all odd words zero => int64
            __shared__ int nz;
            if (t == 0) { nz = 0; g_loss = 0.0f; }
            __syncthreads();
            int a = labels_raw[4 * t + 1] | labels_raw[4 * t + 3];
            if (a != 0) atomicAdd(&nz, 1);
            __syncthreads();
            if (t == 0) g_isI64 = (nz == 0);
        }
    } else {
        size_t i8 = (size_t)(blockIdx.x - MROWS) * 256 + t;
        if (i8 >= NCHUNK8) return;
        float4 a = __ldcs(((const float4*)W) + i8 * 2);
        float4 b = __ldcs(((const float4*)W) + i8 * 2 + 1);
        uint2 lo = f4toh4(a), hi = f4toh4(b);
        ((uint4*)g_wh)[i8] = make_uint4(lo.x, lo.y, hi.x, hi.y);
    }
}

// ---------------------------------------------------------------------------
// Kernel 2: wf = xn @ W^T, fp16 m16n8k16 mma.sync + ldmatrix, cp.async
// 3-stage pipeline, occupancy 1, warp tile 64x64 (128 acc regs), fused
// per-row exp sums via atomics. Streaming wf stores.
// ---------------------------------------------------------------------------
__global__ __launch_bounds__(256, 1)
void gemm_f16(float* __restrict__ wf) {
    extern __shared__ char smem[];

    const int tid   = threadIdx.x;
    const int lane  = tid & 31;
    const int wid   = tid >> 5;
    const int warpM = wid & 3;     // 4 warps in M (64 rows each)
    const int warpN = wid >> 2;    // 2 warps in N (64 cols each)
    const int g     = lane >> 2;
    const int t     = lane & 3;
    const int rowBase = blockIdx.x * BM;
    const int colBase = blockIdx.y * BN;

    const uint32_t sbase = smem_u32(smem);

    float acc[4][8][4];
    #pragma unroll
    for (int mi = 0; mi < 4; ++mi)
        #pragma unroll
        for (int ni = 0; ni < 8; ++ni)
            #pragma unroll
            for (int r = 0; r < 4; ++r) acc[mi][ni][r] = 0.0f;

    // cp.async mapping. A: 2048 16B-chunks, 8/thread at row stride 32.
    // B: 1024 chunks, 4/thread at row stride 32.
    const int cS  = tid & 7;
    const int r0  = tid >> 3;                       // 0..31
    const uint32_t dA0 = swz(r0, cS);               // +i*4096 per chunk
    const uint32_t dB0 = AST + swz(r0, cS);
    const __half* gAb = g_xnh + (size_t)(rowBase + r0) * KDIM + cS * 8;
    const __half* gB[4];
    uint32_t bSz[4];
    #pragma unroll
    for (int i = 0; i < 4; ++i) {
        int n = colBase + r0 + i * 32;
        bool ok = n < CCLS;
        gB[i] = g_wh + (size_t)(ok ? n : 0) * KDIM + cS * 8;
        bSz[i] = ok ? 16u : 0u;
    }

    auto cp_stage = [&](int slot, int ko) {
        uint32_t base = sbase + slot * STAGE_BYTES;
        #pragma unroll
        for (int i = 0; i < 8; ++i)
            cp16(base + dA0 + i * 4096, gAb + ko + (size_t)i * 32 * KDIM, 16);
        #pragma unroll
        for (int i = 0; i < 4; ++i)
            cp16(base + dB0 + i * 4096, gB[i] + ko, bSz[i]);
    };

    // ldmatrix per-lane addressing
    const int rIn  = lane & 15;
    const int kHal = lane >> 4;

    auto compute = [&](int slot) {
        const uint32_t aBase = sbase + slot * STAGE_BYTES;
        const uint32_t bBase = aBase + AST;
        #pragma unroll
        for (int ks = 0; ks < 4; ++ks) {
            const int c16 = ks * 2 + kHal;
            uint32_t af[4][4], bf[4][4];
            #pragma unroll
            for (int mi = 0; mi < 4; ++mi)
                ldsm4(af[mi], aBase + swz(warpM * 64 + mi * 16 + rIn, c16));
            #pragma unroll
            for (int nb = 0; nb < 4; ++nb)
                ldsm4(bf[nb], bBase + swz(warpN * 64 + nb * 16 + rIn, c16));
            #pragma unroll
            for (int mi = 0; mi < 4; ++mi)
                #pragma unroll
                for (int ni = 0; ni < 8; ++ni)
                    mma_f16(acc[mi][ni], af[mi],
                            bf[ni >> 1][ni & 1], bf[ni >> 1][(ni & 1) + 2]);
        }
    };

    // prologue: fill stages 0,1
    cp_stage(0, 0);  cp_commit();
    cp_stage(1, BK); cp_commit();

    #pragma unroll 1
    for (int kb = 0; kb < KSTAGES; ++kb) {
        cp_wait<1>();          // stage kb arrived
        __syncthreads();       // visible to all warps; prior compute done
        if (kb + 2 < KSTAGES) cp_stage((kb + 2) % NSTAGE, (kb + 2) * BK);
        cp_commit();           // keep group counting uniform
        compute(kb % NSTAGE);
    }

    // epilogue: streaming float2 stores (nG even & CCLS even -> pair valid) +
    // fused exp rowsums
    #pragma unroll
    for (int mi = 0; mi < 4; ++mi) {
        int mG0 = rowBase + warpM * 64 + mi * 16 + g;
        int mG1 = mG0 + 8;
        float s0 = 0.0f, s1 = 0.0f;
        #pragma unroll
        for (int ni = 0; ni < 8; ++ni) {
            int nG = colBase + warpN * 64 + ni * 8 + 2 * t;
            float c0 = acc[mi][ni][0], c1 = acc[mi][ni][1];
            float c2 = acc[mi][ni][2], c3 = acc[mi][ni][3];
            if (nG < CCLS) {
                stg_cs2(wf + (size_t)mG0 * CCLS + nG, c0, c1);
                stg_cs2(wf + (size_t)mG1 * CCLS + nG, c2, c3);
                s0 += __expf(S_SCALE * c0) + __expf(S_SCALE * c1);
                s1 += __expf(S_SCALE * c2) + __expf(S_SCALE * c3);
            }
        }
        s0 += __shfl_xor_sync(0xffffffffu, s0, 1);
        s0 += __shfl_xor_sync(0xffffffffu, s0, 2);
        s1 += __shfl_xor_sync(0xffffffffu, s1, 1);
        s1 += __shfl_xor_sync(0xffffffffu, s1, 2);
        if (t == 0) {
            atomicAdd(&g_rowsum[mG0], s0);
            atomicAdd(&g_rowsum[mG1], s1);
        }
    }
}

// ---------------------------------------------------------------------------
// Kernel 3: arcface loss partials. 16 blocks x 64 threads (one per sample),
// partial sums atomically into g_loss. Kernel 4 finalizes.
// ---------------------------------------------------------------------------
__global__ void loss_partial(const float* __restrict__ wf,
                             const int* __restrict__ labels_raw) {
    int i = blockIdx.x * 64 + threadIdx.x;   // 0..1023

    int lab;
    if (g_isI64) lab = (int)((const long long*)labels_raw)[i];
    else         lab = labels_raw[i];

    float tgt = wf[(size_t)i * CCLS + lab];
    float tc  = fminf(fmaxf(tgt, -1.0f + EPS_CL), 1.0f - EPS_CL);
    float num = S_SCALE * cosf(acosf(tc) + MARGIN);
    float excl  = g_rowsum[i] - __expf(S_SCALE * tgt);
    float denom = __expf(num) + excl;
    float L = num - logf(denom);

    #pragma unroll
    for (int o = 16; o > 0; o >>= 1) L += __shfl_xor_sync(0xffffffffu, L, o);
    __shared__ float w0;
    if (threadIdx.x == 0) w0 = L;
    __syncthreads();
    if (threadIdx.x == 32) atomicAdd(&g_loss, w0 + L);
}

__global__ void loss_final(float* __restrict__ out, int lossIdx) {
    out[lossIdx] = -(g_loss * (1.0f / 1024.0f));
}

// ---------------------------------------------------------------------------
extern "C" void kernel_launch(void* const* d_in, const int* in_sizes, int n_in,
                              void* d_out, int out_size) {
    const float* x      = (const float*)d_in[0];   // [1024, 512] f32
    const float* W      = (const float*)d_in[1];   // [85742, 512] f32
    const int*   labels = (const int*)d_in[2];     // [1024] int32 or int64
    float* out = (float*)d_out;                    // wf [1024*85742] ++ loss

    prep_kernel<<<MROWS + CONVBLK, 256>>>(x, W, labels);

    cudaFuncSetAttribute(gemm_f16, cudaFuncAttributeMaxDynamicSharedMemorySize,
                         NSTAGE * STAGE_BYTES);
    dim3 grid(MROWS / BM, (CCLS + BN - 1) / BN);   // (4, 670), M fast
    gemm_f16<<<grid, 256, NSTAGE * STAGE_BYTES>>>(out);

    loss_partial<<<16, 64>>>(out, labels);
    loss_final<<<1, 1>>>(out, out_size - 1);
}

// round 11
// speedup vs baseline: 1.2363x; 1.2363x over previous
#include <cuda_runtime.h>
#include <cuda_fp16.h>
#include <math.h>
#include <stdint.h>

#define MROWS 1024
#define KDIM  512
#define CCLS  85742
#define S_SCALE 64.0f
#define MARGIN  0.5f
#define EPS_CL  1e-7f

// GEMM tiling: 128x128 CTA tile, 256 threads (8 warps, 2 M x 4 N, warp 64x32)
// occupancy 2 CTAs/SM. (Proven best config: R8/R9, 322 us.)
#define BM 128
#define BN 128
#define BK 64                    // k-halves per stage -> 128B per smem row
#define KSTAGES (KDIM / BK)      // 8
#define ROWB 128                 // bytes per smem row (SW128 swizzle)
#define AST (BM * ROWB)          // 16384
#define BST (BN * ROWB)          // 16384
#define STAGE_BYTES (AST + BST)  // 32768
#define NSTAGE 3                 // 96KB dynamic smem per CTA

#define NCHUNK16 ((size_t)CCLS * KDIM / 16)      // 32B-output chunks of W
#define CONVBLK ((int)((NCHUNK16 + 255) / 256))  // conv blocks (256 thr)

__device__ __half g_xnh[MROWS * KDIM];          // normalized x, fp16
__device__ __half g_wh[(size_t)CCLS * KDIM];    // W, fp16 (87.8 MB)
__device__ float  g_rowsum[MROWS];
__device__ float  g_loss;
__device__ unsigned g_cnt;
__device__ int    g_isI64;

// ---------------------------------------------------------------------------
// helpers
// ---------------------------------------------------------------------------
__device__ __forceinline__ uint32_t smem_u32(const void* p) {
    uint32_t a;
    asm("{ .reg .u64 t; cvta.to.shared.u64 t, %1; cvt.u32.u64 %0, t; }"
        : "=r"(a) : "l"(p));
    return a;
}

// SW128 swizzle: row r (128B rows), 16B chunk c in [0,8)
__device__ __forceinline__ uint32_t swz(int r, int c) {
    return (uint32_t)(r * ROWB + ((c ^ (r & 7)) << 4));
}

__device__ __forceinline__ uint2 f4toh4(float4 v) {
    __half2 lo = __float22half2_rn(make_float2(v.x, v.y));
    __half2 hi = __float22half2_rn(make_float2(v.z, v.w));
    uint2 r;
    r.x = *reinterpret_cast<unsigned*>(&lo);
    r.y = *reinterpret_cast<unsigned*>(&hi);
    return r;
}

__device__ __forceinline__ void cp16(uint32_t dst, const void* src, uint32_t srcsz) {
    asm volatile("cp.async.cg.shared.global [%0], [%1], 16, %2;"
                 :: "r"(dst), "l"(src), "r"(srcsz) : "memory");
}
__device__ __forceinline__ void cp_commit() {
    asm volatile("cp.async.commit_group;" ::: "memory");
}
template <int N> __device__ __forceinline__ void cp_wait() {
    asm volatile("cp.async.wait_group %0;" :: "n"(N) : "memory");
}

__device__ __forceinline__ void ldsm4(uint32_t* r, uint32_t addr) {
    asm volatile("ldmatrix.sync.aligned.m8n8.x4.shared.b16 {%0,%1,%2,%3}, [%4];"
                 : "=r"(r[0]), "=r"(r[1]), "=r"(r[2]), "=r"(r[3]) : "r"(addr));
}

__device__ __forceinline__ void mma_f16(float* d, const uint32_t* a,
                                        uint32_t b0, uint32_t b1) {
    asm volatile(
        "mma.sync.aligned.m16n8k16.row.col.f32.f16.f16.f32 "
        "{%0,%1,%2,%3}, {%4,%5,%6,%7}, {%8,%9}, {%0,%1,%2,%3};"
        : "+f"(d[0]), "+f"(d[1]), "+f"(d[2]), "+f"(d[3])
        : "r"(a[0]), "r"(a[1]), "r"(a[2]), "r"(a[3]), "r"(b0), "r"(b1));
}

__device__ __forceinline__ void stg_cs2(float* p, float a, float b) {
    asm volatile("st.global.cs.v2.f32 [%0], {%1,%2};"
                 :: "l"(p), "f"(a), "f"(b) : "memory");
}

// ---------------------------------------------------------------------------
// Kernel 1 (prep): blocks [0,1024) L2-normalize one x-row each into g_xnh and
// zero g_rowsum (block 0 also zeroes g_loss/g_cnt and sniffs label dtype);
// blocks [1024, 1024+CONVBLK) convert W f32 -> fp16, 16 elems/thread, __ldcs.
// ---------------------------------------------------------------------------
__global__ void prep_kernel(const float* __restrict__ x,
                            const float* __restrict__ W,
                            const int* __restrict__ labels_raw) {
    int t = threadIdx.x;            // 256 threads
    if (blockIdx.x < MROWS) {
        int row = blockIdx.x;
        float s = 0.0f;
        float4 v = make_float4(0.f, 0.f, 0.f, 0.f);
        if (t < 128) {
            v = ((const float4*)(x + (size_t)row * KDIM))[t];
            s = v.x * v.x + v.y * v.y + v.z * v.z + v.w * v.w;
        }
        #pragma unroll
        for (int o = 16; o > 0; o >>= 1) s += __shfl_xor_sync(0xffffffffu, s, o);
        __shared__ float ws[8];
        int lane = t & 31, wid = t >> 5;
        if (lane == 0) ws[wid] = s;
        __syncthreads();
        float tot = ws[0] + ws[1] + ws[2] + ws[3];
        float inv = 1.0f / fmaxf(sqrtf(tot), 1e-12f);
        if (t < 128) {
            float4 o4 = make_float4(v.x * inv, v.y * inv, v.z * inv, v.w * inv);
            ((uint2*)(g_xnh + (size_t)row * KDIM))[t] = f4toh4(o4);
        }
        if (t == 0) g_rowsum[row] = 0.0f;

        if (row == 0) {
            // label dtype sniff on words [0,1024): all odd words zero => int64
            __shared__ int nz;
            if (t == 0) { nz = 0; g_loss = 0.0f; g_cnt = 0u; }
            __syncthreads();
            int a = labels_raw[4 * t + 1] | labels_raw[4 * t + 3];
            if (a != 0) atomicAdd(&nz, 1);
            __syncthreads();
            if (t == 0) g_isI64 = (nz == 0);
        }
    } else {
        size_t i16 = (size_t)(blockIdx.x - MROWS) * 256 + t;
        if (i16 >= NCHUNK16) return;
        float4 a = __ldcs(((const float4*)W) + i16 * 4);
        float4 b = __ldcs(((const float4*)W) + i16 * 4 + 1);
        float4 c = __ldcs(((const float4*)W) + i16 * 4 + 2);
        float4 d = __ldcs(((const float4*)W) + i16 * 4 + 3);
        uint2 l0 = f4toh4(a), h0 = f4toh4(b);
        uint2 l1 = f4toh4(c), h1 = f4toh4(d);
        ((uint4*)g_wh)[i16 * 2]     = make_uint4(l0.x, l0.y, h0.x, h0.y);
        ((uint4*)g_wh)[i16 * 2 + 1] = make_uint4(l1.x, l1.y, h1.x, h1.y);
    }
}

// ---------------------------------------------------------------------------
// Kernel 2: wf = xn @ W^T, fp16 m16n8k16 mma.sync + ldmatrix, cp.async
// 3-stage pipeline, occupancy 2, fused per-row exp sums via atomics.
// wf stores use st.global.cs (streaming). [Unchanged from 322us config.]
// ---------------------------------------------------------------------------
__global__ __launch_bounds__(256, 2)
void gemm_f16(float* __restrict__ wf) {
    extern __shared__ char smem[];

    const int tid   = threadIdx.x;
    const int lane  = tid & 31;
    const int wid   = tid >> 5;
    const int warpM = wid & 1;     // 2 warps in M (64 rows each)
    const int warpN = wid >> 1;    // 4 warps in N (32 cols each)
    const int g     = lane >> 2;
    const int t     = lane & 3;
    const int rowBase = blockIdx.x * BM;
    const int colBase = blockIdx.y * BN;

    const uint32_t sbase = smem_u32(smem);

    float acc[4][4][4];
    #pragma unroll
    for (int mi = 0; mi < 4; ++mi)
        #pragma unroll
        for (int ni = 0; ni < 4; ++ni)
            #pragma unroll
            for (int r = 0; r < 4; ++r) acc[mi][ni][r] = 0.0f;

    // cp.async mapping: 1024 16B-chunks per operand tile, 4 per thread
    const int cS = tid & 7;
    uint32_t dA[4], dB[4];
    const __half* gA[4];
    const __half* gB[4];
    uint32_t bSz[4];
    #pragma unroll
    for (int i = 0; i < 4; ++i) {
        int s = i * 256 + tid, r = s >> 3;
        dA[i] = swz(r, cS);
        dB[i] = AST + swz(r, cS);
        gA[i] = g_xnh + (size_t)(rowBase + r) * KDIM + cS * 8;
        int n = colBase + r;
        bool ok = n < CCLS;
        gB[i] = g_wh + (ok ? (size_t)n * KDIM + cS * 8 : 0);
        bSz[i] = ok ? 16u : 0u;
    }

    auto cp_stage = [&](int slot, int ko) {
        uint32_t base = sbase + slot * STAGE_BYTES;
        #pragma unroll
        for (int i = 0; i < 4; ++i) cp16(base + dA[i], gA[i] + ko, 16);
        #pragma unroll
        for (int i = 0; i < 4; ++i) cp16(base + dB[i], gB[i] + ko, bSz[i]);
    };

    // ldmatrix per-lane addressing
    const int rIn  = lane & 15;
    const int kHal = lane >> 4;

    auto compute = [&](int slot) {
        const uint32_t aBase = sbase + slot * STAGE_BYTES;
        const uint32_t bBase = aBase + AST;
        #pragma unroll
        for (int ks = 0; ks < 4; ++ks) {
            const int c16 = ks * 2 + kHal;
            uint32_t af[4][4], bf[2][4];
            #pragma unroll
            for (int mi = 0; mi < 4; ++mi)
                ldsm4(af[mi], aBase + swz(warpM * 64 + mi * 16 + rIn, c16));
            #pragma unroll
            for (int nb = 0; nb < 2; ++nb)
                ldsm4(bf[nb], bBase + swz(warpN * 32 + nb * 16 + rIn, c16));
            #pragma unroll
            for (int mi = 0; mi < 4; ++mi)
                #pragma unroll
                for (int ni = 0; ni < 4; ++ni)
                    mma_f16(acc[mi][ni], af[mi],
                            bf[ni >> 1][ni & 1], bf[ni >> 1][(ni & 1) + 2]);
        }
    };

    // prologue: fill stages 0,1
    cp_stage(0, 0);  cp_commit();
    cp_stage(1, BK); cp_commit();

    #pragma unroll 1
    for (int kb = 0; kb < KSTAGES; ++kb) {
        cp_wait<1>();          // stage kb arrived
        __syncthreads();       // visible to all warps; prior compute done
        if (kb + 2 < KSTAGES) cp_stage((kb + 2) % NSTAGE, (kb + 2) * BK);
        cp_commit();           // keep group counting uniform
        compute(kb % NSTAGE);
    }

    // epilogue: streaming float2 stores (nG even & CCLS even -> pair valid) +
    // fused exp rowsums
    #pragma unroll
    for (int mi = 0; mi < 4; ++mi) {
        int mG0 = rowBase + warpM * 64 + mi * 16 + g;
        int mG1 = mG0 + 8;
        float s0 = 0.0f, s1 = 0.0f;
        #pragma unroll
        for (int ni = 0; ni < 4; ++ni) {
            int nG = colBase + warpN * 32 + ni * 8 + 2 * t;
            float c0 = acc[mi][ni][0], c1 = acc[mi][ni][1];
            float c2 = acc[mi][ni][2], c3 = acc[mi][ni][3];
            if (nG < CCLS) {
                stg_cs2(wf + (size_t)mG0 * CCLS + nG, c0, c1);
                stg_cs2(wf + (size_t)mG1 * CCLS + nG, c2, c3);
                s0 += __expf(S_SCALE * c0) + __expf(S_SCALE * c1);
                s1 += __expf(S_SCALE * c2) + __expf(S_SCALE * c3);
            }
        }
        s0 += __shfl_xor_sync(0xffffffffu, s0, 1);
        s0 += __shfl_xor_sync(0xffffffffu, s0, 2);
        s1 += __shfl_xor_sync(0xffffffffu, s1, 1);
        s1 += __shfl_xor_sync(0xffffffffu, s1, 2);
        if (t == 0) {
            atomicAdd(&g_rowsum[mG0], s0);
            atomicAdd(&g_rowsum[mG1], s1);
        }
    }
}

// ---------------------------------------------------------------------------
// Kernel 3: arcface loss. 16 blocks x 64 threads (one sample per thread),
// partial sums atomically into g_loss; the LAST block to finish writes the
// final scalar (completion-counter pattern), removing the finalize launch.
// ---------------------------------------------------------------------------
__global__ void loss_kernel(const float* __restrict__ wf,
                            const int* __restrict__ labels_raw,
                            float* __restrict__ out, int lossIdx) {
    int i = blockIdx.x * 64 + threadIdx.x;   // 0..1023

    int lab;
    if (g_isI64) lab = (int)((const long long*)labels_raw)[i];
    else         lab = labels_raw[i];

    float tgt = wf[(size_t)i * CCLS + lab];
    float tc  = fminf(fmaxf(tgt, -1.0f + EPS_CL), 1.0f - EPS_CL);
    float num = S_SCALE * cosf(acosf(tc) + MARGIN);
    float excl  = g_rowsum[i] - __expf(S_SCALE * tgt);
    float denom = __expf(num) + excl;
    float L = num - logf(denom);

    #pragma unroll
    for (int o = 16; o > 0; o >>= 1) L += __shfl_xor_sync(0xffffffffu, L, o);
    __shared__ float w0;
    __shared__ bool last;
    if (threadIdx.x == 0) w0 = L;
    __syncthreads();
    if (threadIdx.x == 32) {
        atomicAdd(&g_loss, w0 + L);
        __threadfence();
        unsigned done = atomicAdd(&g_cnt, 1u);
        last = (done == gridDim.x - 1);
    }
    __syncthreads();
    if (last && threadIdx.x == 0) {
        __threadfence();
        out[lossIdx] = -(g_loss * (1.0f / 1024.0f));
    }
}

// ---------------------------------------------------------------------------
extern "C" void kernel_launch(void* const* d_in, const int* in_sizes, int n_in,
                              void* d_out, int out_size) {
    const float* x      = (const float*)d_in[0];   // [1024, 512] f32
    const float* W      = (const float*)d_in[1];   // [85742, 512] f32
    const int*   labels = (const int*)d_in[2];     // [1024] int32 or int64
    float* out = (float*)d_out;                    // wf [1024*85742] ++ loss

    prep_kernel<<<MROWS + CONVBLK, 256>>>(x, W, labels);

    cudaFuncSetAttribute(gemm_f16, cudaFuncAttributeMaxDynamicSharedMemorySize,
                         NSTAGE * STAGE_BYTES);
    dim3 grid(MROWS / BM, (CCLS + BN - 1) / BN);   // (8, 670), M fast
    gemm_f16<<<grid, 256, NSTAGE * STAGE_BYTES>>>(out);

    loss_kernel<<<16, 64>>>(out, labels, out, out_size - 1);
}

// round 12
// speedup vs baseline: 1.2552x; 1.0153x over previous
#include <cuda_runtime.h>
#include <cuda_fp16.h>
#include <math.h>
#include <stdint.h>

#define MROWS 1024
#define KDIM  512
#define CCLS  85742
#define S_SCALE 64.0f
#define MARGIN  0.5f
#define EPS_CL  1e-7f

// GEMM tiling: 128x128 CTA tile, 128 threads (4 warps, 2 M x 2 N, warp 64x64)
// occupancy 2 CTAs/SM. Halves LDSM fragment redundancy vs 8-warp layout.
#define BM 128
#define BN 128
#define BK 64                    // k-halves per stage -> 128B per smem row
#define KSTAGES (KDIM / BK)      // 8
#define ROWB 128                 // bytes per smem row (SW128 swizzle)
#define AST (BM * ROWB)          // 16384
#define BST (BN * ROWB)          // 16384
#define STAGE_BYTES (AST + BST)  // 32768
#define NSTAGE 3                 // 96KB dynamic smem per CTA

#define NCHUNK16 ((size_t)CCLS * KDIM / 16)      // 32B-output chunks of W
#define CONVBLK ((int)((NCHUNK16 + 255) / 256))  // conv blocks (256 thr)

__device__ __half g_xnh[MROWS * KDIM];          // normalized x, fp16
__device__ __half g_wh[(size_t)CCLS * KDIM];    // W, fp16 (87.8 MB)
__device__ float  g_rowsum[MROWS];
__device__ float  g_loss;
__device__ unsigned g_cnt;
__device__ int    g_isI64;

// ---------------------------------------------------------------------------
// helpers
// ---------------------------------------------------------------------------
__device__ __forceinline__ uint32_t smem_u32(const void* p) {
    uint32_t a;
    asm("{ .reg .u64 t; cvta.to.shared.u64 t, %1; cvt.u32.u64 %0, t; }"
        : "=r"(a) : "l"(p));
    return a;
}

// SW128 swizzle: row r (128B rows), 16B chunk c in [0,8)
__device__ __forceinline__ uint32_t swz(int r, int c) {
    return (uint32_t)(r * ROWB + ((c ^ (r & 7)) << 4));
}

__device__ __forceinline__ uint2 f4toh4(float4 v) {
    __half2 lo = __float22half2_rn(make_float2(v.x, v.y));
    __half2 hi = __float22half2_rn(make_float2(v.z, v.w));
    uint2 r;
    r.x = *reinterpret_cast<unsigned*>(&lo);
    r.y = *reinterpret_cast<unsigned*>(&hi);
    return r;
}

__device__ __forceinline__ void cp16(uint32_t dst, const void* src, uint32_t srcsz) {
    asm volatile("cp.async.cg.shared.global [%0], [%1], 16, %2;"
                 :: "r"(dst), "l"(src), "r"(srcsz) : "memory");
}
__device__ __forceinline__ void cp_commit() {
    asm volatile("cp.async.commit_group;" ::: "memory");
}
template <int N> __device__ __forceinline__ void cp_wait() {
    asm volatile("cp.async.wait_group %0;" :: "n"(N) : "memory");
}

__device__ __forceinline__ void ldsm4(uint32_t* r, uint32_t addr) {
    asm volatile("ldmatrix.sync.aligned.m8n8.x4.shared.b16 {%0,%1,%2,%3}, [%4];"
                 : "=r"(r[0]), "=r"(r[1]), "=r"(r[2]), "=r"(r[3]) : "r"(addr));
}

__device__ __forceinline__ void mma_f16(float* d, const uint32_t* a,
                                        uint32_t b0, uint32_t b1) {
    asm volatile(
        "mma.sync.aligned.m16n8k16.row.col.f32.f16.f16.f32 "
        "{%0,%1,%2,%3}, {%4,%5,%6,%7}, {%8,%9}, {%0,%1,%2,%3};"
        : "+f"(d[0]), "+f"(d[1]), "+f"(d[2]), "+f"(d[3])
        : "r"(a[0]), "r"(a[1]), "r"(a[2]), "r"(a[3]), "r"(b0), "r"(b1));
}

__device__ __forceinline__ void stg_cs2(float* p, float a, float b) {
    asm volatile("st.global.cs.v2.f32 [%0], {%1,%2};"
                 :: "l"(p), "f"(a), "f"(b) : "memory");
}

// ---------------------------------------------------------------------------
// Kernel 1 (prep): blocks [0,1024) L2-normalize one x-row each into g_xnh and
// zero g_rowsum (block 0 also zeroes g_loss/g_cnt and sniffs label dtype);
// blocks [1024, 1024+CONVBLK) convert W f32 -> fp16, 16 elems/thread, __ldcs.
// ---------------------------------------------------------------------------
__global__ void prep_kernel(const float* __restrict__ x,
                            const float* __restrict__ W,
                            const int* __restrict__ labels_raw) {
    int t = threadIdx.x;            // 256 threads
    if (blockIdx.x < MROWS) {
        int row = blockIdx.x;
        float s = 0.0f;
        float4 v = make_float4(0.f, 0.f, 0.f, 0.f);
        if (t < 128) {
            v = ((const float4*)(x + (size_t)row * KDIM))[t];
            s = v.x * v.x + v.y * v.y + v.z * v.z + v.w * v.w;
        }
        #pragma unroll
        for (int o = 16; o > 0; o >>= 1) s += __shfl_xor_sync(0xffffffffu, s, o);
        __shared__ float ws[8];
        int lane = t & 31, wid = t >> 5;
        if (lane == 0) ws[wid] = s;
        __syncthreads();
        float tot = ws[0] + ws[1] + ws[2] + ws[3];
        float inv = 1.0f / fmaxf(sqrtf(tot), 1e-12f);
        if (t < 128) {
            float4 o4 = make_float4(v.x * inv, v.y * inv, v.z * inv, v.w * inv);
            ((uint2*)(g_xnh + (size_t)row * KDIM))[t] = f4toh4(o4);
        }
        if (t == 0) g_rowsum[row] = 0.0f;

        if (row == 0) {
            // label dtype sniff on words [0,1024): all odd words zero => int64
            __shared__ int nz;
            if (t == 0) { nz = 0; g_loss = 0.0f; g_cnt = 0u; }
            __syncthreads();
            int a = labels_raw[4 * t + 1] | labels_raw[4 * t + 3];
            if (a != 0) atomicAdd(&nz, 1);
            __syncthreads();
            if (t == 0) g_isI64 = (nz == 0);
        }
    } else {
        size_t i16 = (size_t)(blockIdx.x - MROWS) * 256 + t;
        if (i16 >= NCHUNK16) return;
        float4 a = __ldcs(((const float4*)W) + i16 * 4);
        float4 b = __ldcs(((const float4*)W) + i16 * 4 + 1);
        float4 c = __ldcs(((const float4*)W) + i16 * 4 + 2);
        float4 d = __ldcs(((const float4*)W) + i16 * 4 + 3);
        uint2 l0 = f4toh4(a), h0 = f4toh4(b);
        uint2 l1 = f4toh4(c), h1 = f4toh4(d);
        ((uint4*)g_wh)[i16 * 2]     = make_uint4(l0.x, l0.y, h0.x, h0.y);
        ((uint4*)g_wh)[i16 * 2 + 1] = make_uint4(l1.x, l1.y, h1.x, h1.y);
    }
}

// ---------------------------------------------------------------------------
// Kernel 2: wf = xn @ W^T, fp16 m16n8k16 mma.sync + ldmatrix, cp.async
// 3-stage pipeline, occupancy 2, 4 warps of 64x64, fused per-row exp sums.
// ---------------------------------------------------------------------------
__global__ __launch_bounds__(128, 2)
void gemm_f16(float* __restrict__ wf) {
    extern __shared__ char smem[];

    const int tid   = threadIdx.x;
    const int lane  = tid & 31;
    const int wid   = tid >> 5;
    const int warpM = wid & 1;     // 2 warps in M (64 rows each)
    const int warpN = wid >> 1;    // 2 warps in N (64 cols each)
    const int g     = lane >> 2;
    const int t     = lane & 3;
    const int rowBase = blockIdx.x * BM;
    const int colBase = blockIdx.y * BN;

    const uint32_t sbase = smem_u32(smem);

    float acc[4][8][4];
    #pragma unroll
    for (int mi = 0; mi < 4; ++mi)
        #pragma unroll
        for (int ni = 0; ni < 8; ++ni)
            #pragma unroll
            for (int r = 0; r < 4; ++r) acc[mi][ni][r] = 0.0f;

    // cp.async mapping: 1024 16B-chunks per operand tile, 8 per thread.
    // r0 = tid>>3 in [0,16), chunk rows r0 + 16*i; cS = tid&7.
    const int cS = tid & 7;
    const int r0 = tid >> 3;
    const uint32_t dA0 = swz(r0, cS);          // +i*2048 per 16-row step
    const uint32_t dB0 = AST + swz(r0, cS);
    const __half* gAb = g_xnh + (size_t)(rowBase + r0) * KDIM + cS * 8;
    const __half* gWb = g_wh + (size_t)(colBase + r0) * KDIM + cS * 8;

    auto cp_stage = [&](int slot, int ko) {
        uint32_t base = sbase + slot * STAGE_BYTES;
        #pragma unroll
        for (int i = 0; i < 8; ++i)
            cp16(base + dA0 + i * 2048, gAb + ko + (size_t)i * 16 * KDIM, 16);
        #pragma unroll
        for (int i = 0; i < 8; ++i) {
            int n = colBase + r0 + i * 16;
            bool ok = n < CCLS;
            const __half* src = ok ? gWb + ko + (size_t)i * 16 * KDIM : (const __half*)g_wh;
            cp16(base + dB0 + i * 2048, src, ok ? 16u : 0u);
        }
    };

    // ldmatrix per-lane addressing
    const int rIn  = lane & 15;
    const int kHal = lane >> 4;

    auto compute = [&](int slot) {
        const uint32_t aBase = sbase + slot * STAGE_BYTES;
        const uint32_t bBase = aBase + AST;
        #pragma unroll
        for (int ks = 0; ks < 4; ++ks) {
            const int c16 = ks * 2 + kHal;
            uint32_t af[4][4], bf[4][4];
            #pragma unroll
            for (int mi = 0; mi < 4; ++mi)
                ldsm4(af[mi], aBase + swz(warpM * 64 + mi * 16 + rIn, c16));
            #pragma unroll
            for (int nb = 0; nb < 4; ++nb)
                ldsm4(bf[nb], bBase + swz(warpN * 64 + nb * 16 + rIn, c16));
            #pragma unroll
            for (int mi = 0; mi < 4; ++mi)
                #pragma unroll
                for (int ni = 0; ni < 8; ++ni)
                    mma_f16(acc[mi][ni], af[mi],
                            bf[ni >> 1][ni & 1], bf[ni >> 1][(ni & 1) + 2]);
        }
    };

    // prologue: fill stages 0,1
    cp_stage(0, 0);  cp_commit();
    cp_stage(1, BK); cp_commit();

    #pragma unroll 1
    for (int kb = 0; kb < KSTAGES; ++kb) {
        cp_wait<1>();          // stage kb arrived
        __syncthreads();       // visible to all warps; prior compute done
        if (kb + 2 < KSTAGES) cp_stage((kb + 2) % NSTAGE, (kb + 2) * BK);
        cp_commit();           // keep group counting uniform
        compute(kb % NSTAGE);
    }

    // epilogue: streaming float2 stores (nG even & CCLS even -> pair valid) +
    // fused exp rowsums
    #pragma unroll
    for (int mi = 0; mi < 4; ++mi) {
        int mG0 = rowBase + warpM * 64 + mi * 16 + g;
        int mG1 = mG0 + 8;
        float s0 = 0.0f, s1 = 0.0f;
        #pragma unroll
        for (int ni = 0; ni < 8; ++ni) {
            int nG = colBase + warpN * 64 + ni * 8 + 2 * t;
            float c0 = acc[mi][ni][0], c1 = acc[mi][ni][1];
            float c2 = acc[mi][ni][2], c3 = acc[mi][ni][3];
            if (nG < CCLS) {
                stg_cs2(wf + (size_t)mG0 * CCLS + nG, c0, c1);
                stg_cs2(wf + (size_t)mG1 * CCLS + nG, c2, c3);
                s0 += __expf(S_SCALE * c0) + __expf(S_SCALE * c1);
                s1 += __expf(S_SCALE * c2) + __expf(S_SCALE * c3);
            }
        }
        s0 += __shfl_xor_sync(0xffffffffu, s0, 1);
        s0 += __shfl_xor_sync(0xffffffffu, s0, 2);
        s1 += __shfl_xor_sync(0xffffffffu, s1, 1);
        s1 += __shfl_xor_sync(0xffffffffu, s1, 2);
        if (t == 0) {
            atomicAdd(&g_rowsum[mG0], s0);
            atomicAdd(&g_rowsum[mG1], s1);
        }
    }
}

// ---------------------------------------------------------------------------
// Kernel 3: arcface loss. 16 blocks x 64 threads (one sample per thread),
// partial sums atomically into g_loss; last block writes the final scalar.
// ---------------------------------------------------------------------------
__global__ void loss_kernel(const float* __restrict__ wf,
                            const int* __restrict__ labels_raw,
                            float* __restrict__ out, int lossIdx) {
    int i = blockIdx.x * 64 + threadIdx.x;   // 0..1023

    int lab;
    if (g_isI64) lab = (int)((const long long*)labels_raw)[i];
    else         lab = labels_raw[i];

    float tgt = wf[(size_t)i * CCLS + lab];
    float tc  = fminf(fmaxf(tgt, -1.0f + EPS_CL), 1.0f - EPS_CL);
    float num = S_SCALE * cosf(acosf(tc) + MARGIN);
    float excl  = g_rowsum[i] - __expf(S_SCALE * tgt);
    float denom = __expf(num) + excl;
    float L = num - logf(denom);

    #pragma unroll
    for (int o = 16; o > 0; o >>= 1) L += __shfl_xor_sync(0xffffffffu, L, o);
    __shared__ float w0;
    __shared__ bool last;
    if (threadIdx.x == 0) w0 = L;
    __syncthreads();
    if (threadIdx.x == 32) {
        atomicAdd(&g_loss, w0 + L);
        __threadfence();
        unsigned done = atomicAdd(&g_cnt, 1u);
        last = (done == gridDim.x - 1);
    }
    __syncthreads();
    if (last && threadIdx.x == 0) {
        __threadfence();
        out[lossIdx] = -(g_loss * (1.0f / 1024.0f));
    }
}

// ---------------------------------------------------------------------------
extern "C" void kernel_launch(void* const* d_in, const int* in_sizes, int n_in,
                              void* d_out, int out_size) {
    const float* x      = (const float*)d_in[0];   // [1024, 512] f32
    const float* W      = (const float*)d_in[1];   // [85742, 512] f32
    const int*   labels = (const int*)d_in[2];     // [1024] int32 or int64
    float* out = (float*)d_out;                    // wf [1024*85742] ++ loss

    prep_kernel<<<MROWS + CONVBLK, 256>>>(x, W, labels);

    cudaFuncSetAttribute(gemm_f16, cudaFuncAttributeMaxDynamicSharedMemorySize,
                         NSTAGE * STAGE_BYTES);
    dim3 grid(MROWS / BM, (CCLS + BN - 1) / BN);   // (8, 670), M fast
    gemm_f16<<<grid, 128, NSTAGE * STAGE_BYTES>>>(out);

    loss_kernel<<<16, 64>>>(out, labels, out, out_size - 1);
}